// round 5
// baseline (speedup 1.0000x reference)
#include <cuda_runtime.h>
#include <cuda_bf16.h>

#define FULL 0xffffffffu
typedef unsigned long long u64;

// Packed f32x2 primitives (sm_103a FFMA2 path, PTX-only)
#define MK2(d, lo, hi)   asm("mov.b64 %0, {%1, %2};" : "=l"(d) : "f"(lo), "f"(hi))
#define UP2(lo, hi, s)   asm("mov.b64 {%0, %1}, %2;" : "=f"(lo), "=f"(hi) : "l"(s))
#define PMUL(d, a, b)    asm("mul.rn.f32x2 %0, %1, %2;" : "=l"(d) : "l"(a), "l"(b))
#define PFMA(d, a, b, c) asm("fma.rn.f32x2 %0, %1, %2, %3;" : "=l"(d) : "l"(a), "l"(b), "l"(c))
#define PADD(d, a, b)    asm("add.rn.f32x2 %0, %1, %2;" : "=l"(d) : "l"(a), "l"(b))

__device__ __forceinline__ u64 paxpby(u64 A, u64 X, u64 B, u64 Y) {
    u64 t, d; PMUL(t, B, Y); PFMA(d, A, X, t); return d;
}
__device__ __forceinline__ u64 dup2(float v) { u64 d; MK2(d, v, v); return d; }

// Layout: 2 batch elements per warp (16 lanes each; element = lane>>4).
// Amplitude index i: bits 0-3 = lane bits, bits 4-7 = register bits.
// Register bit0 = slot within a 64-bit pack (packs srp[0..7]); pack index j
// carries reg bits 1-3 (i bits 5-7).  Qubit q lives on amplitude bit (7-q).

__global__ void __launch_bounds__(128)
vqc_kernel(const float* __restrict__ x,         // (B, 4, 8)
           const float* __restrict__ crx_theta, // (10,)
           const float* __restrict__ w1,        // (10, 2)
           const float* __restrict__ b1,        // (10,)
           const float* __restrict__ w2,        // (1, 10)
           const float* __restrict__ b2,        // (1,)
           float* __restrict__ out,             // (B, 1)
           int n_batch) {
    const int pair = (int)((blockIdx.x * blockDim.x + threadIdx.x) >> 5);
    const int lane = threadIdx.x & 31;
    const int e0   = pair * 2;
    if (e0 >= n_batch) return;
    const int half = lane & 16;
    const int lo   = lane & 15;

    const bool has1 = (e0 + 1) < n_batch;
    const int  off  = (half && !has1) ? lo : (lo | (half << 1));
    const float* xb = x + (size_t)e0 * 32;
    float aP = xb[off];
    float aQ = xb[off + 16];
    float Pc, Ps, Qc, Qs;
    __sincosf(0.5f * aP, &Ps, &Pc);
    __sincosf(0.5f * aQ, &Qs, &Qc);

    float th = __ldg(&crx_theta[lo < 10 ? lo : 0]);
    float csn, cco;
    __sincosf(0.5f * th, &csn, &cco);

    u64 srp[8], sip[8];

    // ---------------- Cycle 0: closed form ----------------
    {
        float cq[8], sq[8];
        #pragma unroll
        for (int q = 0; q < 8; q++) {
            cq[q] = __shfl_sync(FULL, Pc, half | q);
            sq[q] = __shfl_sync(FULL, Ps, half | q);
        }
        const int x0 = lane & 1, x1 = (lane >> 1) & 1, x2 = (lane >> 2) & 1, x3 = (lane >> 3) & 1;
        float F0 = (x0 ^ x1) ? sq[7] : cq[7];
        float F1 = (x1 ^ x2) ? sq[6] : cq[6];
        float F2 = (x2 ^ x3) ? sq[5] : cq[5];
        float Plane = F0 * F1 * F2;
        float PB0 = Plane * (x3 ? sq[4] : cq[4]);
        float PB1 = Plane * (x3 ? cq[4] : sq[4]);
        float f6_0 = x0 ? sq[1] : cq[1];
        float f6_1 = x0 ? cq[1] : sq[1];
        float f7_0 = x0 ? sq[0] : cq[0];
        float f7_1 = x0 ? cq[0] : sq[0];
        float G0x = PB0 * cq[3], G0y = PB1 * sq[3];
        float G1x = PB0 * sq[3], G1y = PB1 * cq[3];
        #pragma unroll
        for (int j = 0; j < 8; j++) {
            const int b5 = j & 1, b6 = (j >> 1) & 1, b7 = (j >> 2) & 1;
            float w = ((b5 ^ b6) ? sq[2] : cq[2])
                    * ((b6 ^ b7) ? f6_1 : f6_0)
                    * (b7 ? f7_1 : f7_0);
            float l_ = (b5 ? G1x : G0x) * w;
            float h_ = (b5 ? G1y : G0y) * w;
            MK2(srp[j], l_, h_);
        }
    }

    // ---------------- Cycles 1..3: fused RY+CNOT ----------------
    #pragma unroll
    for (int k = 1; k < 4; k++) {
        // Hoist ALL coefficient broadcasts for this cycle: independent of the
        // state chain, so they issue back-to-back while prior FMAs drain.
        float gc[8], gs[8];
        #pragma unroll
        for (int q = 0; q < 8; q++) {
            const int j_ = k * 8 + q;
            if (j_ < 16) { gc[q] = __shfl_sync(FULL, Pc, half | j_);
                           gs[q] = __shfl_sync(FULL, Ps, half | j_); }
            else         { gc[q] = __shfl_sync(FULL, Qc, half | (j_ - 16));
                           gs[q] = __shfl_sync(FULL, Qs, half | (j_ - 16)); }
        }

        // ---- bit7 gate (packs j <-> j+4), k>=2 fused with prev CNOT(0,7) ----
        if (k == 1) {
            u64 CC = dup2(gc[0]), SS = dup2(gs[0]), NS = dup2(-gs[0]);
            #pragma unroll
            for (int j = 0; j < 4; j++) {
                u64 a = srp[j], b = srp[j + 4];
                srp[j]     = paxpby(CC, a, NS, b);
                srp[j + 4] = paxpby(SS, a, CC, b);
            }
        } else {
            bool g = lane & 1;
            u64 AL0 = dup2(g ? -gs[0] : gc[0]), GA0 = dup2(g ? gc[0] : -gs[0]);
            u64 AL1 = dup2(g ?  gs[0] : gc[0]), GA1 = dup2(g ? gc[0] :  gs[0]);
            #pragma unroll
            for (int j = 0; j < 4; j++) {
                u64 a = srp[j], b = srp[j + 4];
                srp[j]     = paxpby(AL0, a, GA0, b);
                srp[j + 4] = paxpby(AL1, b, GA1, a);
            }
        }
        // ---- bit6 gate: pack pairs (j, j|2), CNOT swap if j&4 ----
        {
            u64 CC = dup2(gc[1]), SS = dup2(gs[1]), NS = dup2(-gs[1]);
            #pragma unroll
            for (int j = 0; j < 8; j++) {
                if (!(j & 2)) {
                    const int j2 = j | 2;
                    u64 a = srp[j], b = srp[j2];
                    u64 n0 = paxpby(CC, a, NS, b);
                    u64 n1 = paxpby(SS, a, CC, b);
                    if (j & 4) { srp[j] = n1; srp[j2] = n0; }
                    else       { srp[j] = n0; srp[j2] = n1; }
                }
            }
        }
        // ---- bit5 gate: pack pairs (j, j|1), swap if j&2 ----
        {
            u64 CC = dup2(gc[2]), SS = dup2(gs[2]), NS = dup2(-gs[2]);
            #pragma unroll
            for (int j = 0; j < 8; j += 2) {
                const int j1 = j | 1;
                u64 a = srp[j], b = srp[j1];
                u64 n0 = paxpby(CC, a, NS, b);
                u64 n1 = paxpby(SS, a, CC, b);
                if (j & 2) { srp[j] = n1; srp[j1] = n0; }
                else       { srp[j] = n0; srp[j1] = n1; }
            }
        }
        // ---- bit4 gate (within pack), swap if j&1: reversed-operand packed ----
        {
            u64 CC; MK2(CC, gc[3], gc[3]);
            u64 SV; MK2(SV, -gs[3], gs[3]);   // no-swap:  out = CC*a + SV*rev
            u64 SW; MK2(SW, gs[3], -gs[3]);   // swap:     out = CC*rev + SW*a
            #pragma unroll
            for (int j = 0; j < 8; j++) {
                float a0, a1; UP2(a0, a1, srp[j]);
                u64 rv; MK2(rv, a1, a0);
                if (j & 1) srp[j] = paxpby(CC, rv, SW, srp[j]);
                else       srp[j] = paxpby(CC, srp[j], SV, rv);
            }
        }
        // ---- bit3 gate: lane mask 8, ctrl = slot parity (reg bit0) ----
        {
            float t = ((lane >> 3) & 1) ? gs[4] : -gs[4];
            u64 ALv; MK2(ALv, gc[4], -t);
            u64 GAv; MK2(GAv, t, gc[4]);
            #pragma unroll
            for (int j = 0; j < 8; j++) {
                u64 p = __shfl_xor_sync(FULL, srp[j], 8);
                srp[j] = paxpby(ALv, srp[j], GAv, p);
            }
        }
        // ---- lane gates: bit2 (ctrl lane3), bit1 (ctrl lane2), bit0 (ctrl lane1) ----
        #define LGATE(B, Q) {                                                \
            float t = ((lane >> (B)) & 1) ? gs[Q] : -gs[Q];                  \
            bool  g = (lane >> ((B) + 1)) & 1;                               \
            u64 AL = dup2(g ? -t : gc[Q]);                                   \
            u64 GA = dup2(g ?  gc[Q] : t);                                   \
            _Pragma("unroll")                                                \
            for (int j = 0; j < 8; j++) {                                    \
                u64 p = __shfl_xor_sync(FULL, srp[j], 1 << (B));             \
                srp[j] = paxpby(AL, srp[j], GA, p);                          \
            } }
        LGATE(2, 5)
        LGATE(1, 6)
        LGATE(0, 7)
        #undef LGATE
    }
    // Cycle 3's trailing CNOT(0,7): conditional pack swap (j <-> j+4)
    {
        bool g = lane & 1;
        #pragma unroll
        for (int j = 0; j < 4; j++) {
            u64 a = srp[j], b = srp[j + 4];
            srp[j]     = g ? b : a;
            srp[j + 4] = g ? a : b;
        }
    }

    // Only si pack0 (regs 0,1) is read before written in the CRX chain.
    { float z0 = 0.0f; MK2(sip[0], z0, z0); }

    // ---------------- 10 CRX gates ----------------
    // Hoist all coefficient broadcasts (state-independent).
    float cov[10], snv[10];
    #pragma unroll
    for (int i = 0; i < 10; i++) {
        cov[i] = __shfl_sync(FULL, cco, i);
        snv[i] = __shfl_sync(FULL, csn, i);
    }

    // CRX0: ctrl reg bit3, tgt reg bit2 -> pack pairs (4,6),(5,7); si==0 (RE)
    { const float co = cov[0], sn = snv[0];
      u64 CO = dup2(co), NSN = dup2(-sn);
      #pragma unroll
      for (int j = 4; j < 6; j++) {
          const int jb = j + 2;
          u64 a = srp[j], b = srp[jb];
          PMUL(srp[j],  CO,  a);  PMUL(sip[j],  NSN, b);
          PMUL(srp[jb], CO,  b);  PMUL(sip[jb], NSN, a);
      } }
    // CRX1: ctrl reg bit2, tgt reg bit1 -> (2,3) RE + (6,7) FULL
    { const float co = cov[1], sn = snv[1];
      u64 CO = dup2(co), SN = dup2(sn), NSN = dup2(-sn);
      { u64 a = srp[2], b = srp[3];
        PMUL(srp[2], CO, a);  PMUL(sip[2], NSN, b);
        PMUL(srp[3], CO, b);  PMUL(sip[3], NSN, a); }
      { u64 ar = srp[6], br = srp[7], ai = sip[6], bi = sip[7];
        srp[6] = paxpby(CO, ar, SN,  bi);  sip[6] = paxpby(CO, ai, NSN, br);
        srp[7] = paxpby(CO, br, SN,  ai);  sip[7] = paxpby(CO, bi, NSN, ar); } }
    // CRX2: ctrl reg bit1, tgt reg bit0 (within pack): pack1 RE + packs 3,5,7 FULL
    { const float co = cov[2], sn = snv[2];
      u64 CO = dup2(co), SN = dup2(sn), NSN = dup2(-sn);
      { float a0, a1; UP2(a0, a1, srp[1]);
        u64 rv; MK2(rv, a1, a0);
        PMUL(srp[1], CO, srp[1]);
        PMUL(sip[1], NSN, rv); }
      #pragma unroll
      for (int j = 3; j < 8; j += 2) {
          float r0, r1, i0, i1;
          UP2(r0, r1, srp[j]);  UP2(i0, i1, sip[j]);
          u64 rvr; MK2(rvr, r1, r0);
          u64 rvi; MK2(rvi, i1, i0);
          srp[j] = paxpby(CO, srp[j], SN,  rvi);
          sip[j] = paxpby(CO, sip[j], NSN, rvr);
      } }
    // CRX3: ctrl reg bit0 (odd slot), tgt lane bit3: scalar on odd halves
    { const float co = cov[3], sn = snv[3];
      #pragma unroll
      for (int j = 0; j < 8; j++) {
          float e, o, ei, oi;
          UP2(e, o, srp[j]);  UP2(ei, oi, sip[j]);
          float pr = __shfl_xor_sync(FULL, o, 8);
          float pi = __shfl_xor_sync(FULL, oi, 8);
          float no  = fmaf(co, o,   sn * pi);
          float noi = fmaf(co, oi, -sn * pr);
          MK2(srp[j], e, no);  MK2(sip[j], ei, noi);
      } }
    // CRX4/5/6: lane-ctrl, lane-target (fold ctrl into coefficients)
    #define CRXL(I, CB, MASK) {                                              \
        bool  g    = (lane >> (CB)) & 1;                                     \
        float co_e = g ? cov[I] : 1.0f;                                      \
        float sn_e = g ? snv[I] : 0.0f;                                      \
        u64 COe = dup2(co_e), SNe = dup2(sn_e), NSNe = dup2(-sn_e);          \
        _Pragma("unroll")                                                    \
        for (int j = 0; j < 8; j++) {                                        \
            u64 pr = __shfl_xor_sync(FULL, srp[j], MASK);                    \
            u64 pi = __shfl_xor_sync(FULL, sip[j], MASK);                    \
            srp[j] = paxpby(COe, srp[j], SNe,  pi);                          \
            sip[j] = paxpby(COe, sip[j], NSNe, pr);                          \
        } }
    CRXL(4, 3, 4)
    CRXL(5, 2, 2)
    CRXL(6, 1, 1)
    #undef CRXL
    // CRX7: ctrl lane bit0, tgt reg bit3 -> pack pairs (j, j+4)
    { bool  g    = lane & 1;
      float co_e = g ? cov[7] : 1.0f;
      float sn_e = g ? snv[7] : 0.0f;
      u64 COe = dup2(co_e), SNe = dup2(sn_e), NSNe = dup2(-sn_e);
      #pragma unroll
      for (int j = 0; j < 4; j++) {
          u64 ar = srp[j], ai = sip[j], br = srp[j + 4], bi = sip[j + 4];
          srp[j]     = paxpby(COe, ar, SNe,  bi);
          sip[j]     = paxpby(COe, ai, NSNe, br);
          srp[j + 4] = paxpby(COe, br, SNe,  ai);
          sip[j + 4] = paxpby(COe, bi, NSNe, ar);
      } }
    // CRX8: ctrl reg bit3, tgt reg bit2 -> pack pairs (4,6),(5,7) FULL
    { u64 CO = dup2(cov[8]), SN = dup2(snv[8]), NSN = dup2(-snv[8]);
      #pragma unroll
      for (int j = 4; j < 6; j++) {
          const int jb = j + 2;
          u64 ar = srp[j], ai = sip[j], br = srp[jb], bi = sip[jb];
          srp[j]  = paxpby(CO, ar, SN,  bi);  sip[j]  = paxpby(CO, ai, NSN, br);
          srp[jb] = paxpby(CO, br, SN,  ai);  sip[jb] = paxpby(CO, bi, NSN, ar);
      } }
    // CRX9: ctrl reg bit2, tgt reg bit1 -> pack pairs (2,3),(6,7) FULL
    { u64 CO = dup2(cov[9]), SN = dup2(snv[9]), NSN = dup2(-snv[9]);
      #pragma unroll
      for (int j = 2; j < 8; j += 4) {
          const int jb = j + 1;
          u64 ar = srp[j], ai = sip[j], br = srp[jb], bi = sip[jb];
          srp[j]  = paxpby(CO, ar, SN,  bi);  sip[j]  = paxpby(CO, ai, NSN, br);
          srp[jb] = paxpby(CO, br, SN,  ai);  sip[jb] = paxpby(CO, bi, NSN, ar);
      } }

    // ---------------- Measurement + MLP ----------------
    // slot x accumulates even regs (qubit3 +), slot y odd regs (qubit3 -)
    u64 acc; { float z0 = 0.0f; MK2(acc, z0, z0); }
    #pragma unroll
    for (int j = 0; j < 8; j++) {
        PFMA(acc, srp[j], srp[j], acc);
        PFMA(acc, sip[j], sip[j], acc);
    }
    float S0, S1; UP2(S0, S1, acc);

    float f0  = S0 - S1;
    float tot = S0 + S1;
    float f1  = (lane & 1) ? -tot : tot;
    // Packed butterfly reduction over the 16-lane half
    u64 fv; MK2(fv, f0, f1);
    #pragma unroll
    for (int m = 8; m >= 1; m >>= 1) {
        u64 p = __shfl_xor_sync(FULL, fv, m);
        PADD(fv, fv, p);
    }
    UP2(f0, f1, fv);

    float contrib = 0.0f;
    if (lo < 10) {
        float z = fmaf(f0, __ldg(&w1[lo * 2 + 0]),
                  fmaf(f1, __ldg(&w1[lo * 2 + 1]), __ldg(&b1[lo])));
        contrib = tanhf(z) * __ldg(&w2[lo]);
    }
    #pragma unroll
    for (int m = 8; m >= 1; m >>= 1)
        contrib += __shfl_xor_sync(FULL, contrib, m);

    if (lo == 0) {
        const int e = e0 + (half >> 4);
        if (e < n_batch) {
            float z = contrib + __ldg(&b2[0]);
            out[e] = 1.0f / (1.0f + __expf(-z));
        }
    }
}

extern "C" void kernel_launch(void* const* d_in, const int* in_sizes, int n_in,
                              void* d_out, int out_size) {
    const float* x         = (const float*)d_in[0];
    const float* crx_theta = (const float*)d_in[1];
    const float* w1        = (const float*)d_in[2];
    const float* b1        = (const float*)d_in[3];
    const float* w2        = (const float*)d_in[4];
    const float* b2        = (const float*)d_in[5];
    float* out = (float*)d_out;

    const int n_batch = in_sizes[0] / 32;      // (B,4,8) -> B
    const int pairs   = (n_batch + 1) / 2;
    const int threads = 128;                   // 4 warps (8 elements) per block
    const int blocks  = (pairs + 3) / 4;
    vqc_kernel<<<blocks, threads>>>(x, crx_theta, w1, b1, w2, b2, out, n_batch);
}

// round 6
// speedup vs baseline: 1.1199x; 1.1199x over previous
#include <cuda_runtime.h>
#include <cuda_bf16.h>

#define FULL 0xffffffffu
typedef unsigned long long u64;

// Packed f32x2 primitives (sm_103a FFMA2 path, PTX-only)
#define MK2(d, lo, hi)   asm("mov.b64 %0, {%1, %2};" : "=l"(d) : "f"(lo), "f"(hi))
#define UP2(lo, hi, s)   asm("mov.b64 {%0, %1}, %2;" : "=f"(lo), "=f"(hi) : "l"(s))
#define PMUL(d, a, b)    asm("mul.rn.f32x2 %0, %1, %2;" : "=l"(d) : "l"(a), "l"(b))
#define PFMA(d, a, b, c) asm("fma.rn.f32x2 %0, %1, %2, %3;" : "=l"(d) : "l"(a), "l"(b), "l"(c))
#define PADD(d, a, b)    asm("add.rn.f32x2 %0, %1, %2;" : "=l"(d) : "l"(a), "l"(b))

__device__ __forceinline__ u64 paxpby(u64 A, u64 X, u64 B, u64 Y) {
    u64 t, d; PMUL(t, B, Y); PFMA(d, A, X, t); return d;
}
__device__ __forceinline__ u64 dup2(float v) { u64 d; MK2(d, v, v); return d; }

// Layout: 4 batch elements per warp (8 lanes each; element = lane>>3).
// Amplitude index i: bits 0-2 = lane bits, bits 3-7 = register bits.
// Pack slot = amp bit3; pack index j (4 bits) = amp bits 4-7 (srp[16]/sip[16]).
// Qubit q lives on amplitude bit (7-q).

__global__ void __launch_bounds__(128)
vqc_kernel(const float* __restrict__ x,         // (B, 4, 8)
           const float* __restrict__ crx_theta, // (10,)
           const float* __restrict__ w1,        // (10, 2)
           const float* __restrict__ b1,        // (10,)
           const float* __restrict__ w2,        // (1, 10)
           const float* __restrict__ b2,        // (1,)
           float* __restrict__ out,             // (B, 1)
           int n_batch) {
    const int warp = (int)((blockIdx.x * blockDim.x + threadIdx.x) >> 5);
    const int lane = threadIdx.x & 31;
    const int e0   = warp * 4;
    if (e0 >= n_batch) return;
    const int gb = lane & 24;      // element group base lane
    const int lo = lane & 7;

    // Angles: each of the 8 lanes of an element holds 4 of its 32 angles:
    // indices lo, lo+8, lo+16, lo+24  -> registers acv/asv[0..3] (one per cycle).
    int em = e0 + (lane >> 3);
    int eL = em < n_batch ? em : n_batch - 1;
    const float* xb = x + (size_t)eL * 32;
    float acv[4], asv[4];
    #pragma unroll
    for (int k = 0; k < 4; k++) {
        float a = xb[lo + k * 8];
        __sincosf(0.5f * a, &asv[k], &acv[k]);
    }

    // CRX thetas (batch-uniform): lanes 0-7 hold theta[lo]; lanes 0-1 also theta[8+lo].
    float thA = __ldg(&crx_theta[lo]);
    float thB = __ldg(&crx_theta[lo < 2 ? 8 + lo : 8]);
    float csnA, ccoA, csnB, ccoB;
    __sincosf(0.5f * thA, &csnA, &ccoA);
    __sincosf(0.5f * thB, &csnB, &ccoB);

    u64 srp[16], sip[16];

    // ---------------- Cycle 0: closed form ----------------
    // amp[i] = prod_b F_b(v_b(i)); v0=i0^i1 v1=i1^i2 v2=i2^i3 v3=i3^i4
    // v4=i4^i5 v5=i5^i6 v6=i0^i6^i7 v7=i0^i7; F_b uses qubit 7-b's (cos,sin).
    {
        float cq[8], sq[8];
        #pragma unroll
        for (int q = 0; q < 8; q++) {
            cq[q] = __shfl_sync(FULL, acv[0], gb | q);
            sq[q] = __shfl_sync(FULL, asv[0], gb | q);
        }
        const int x0 = lane & 1, x1 = (lane >> 1) & 1, x2 = (lane >> 2) & 1;
        float Lbase = ((x0 ^ x1) ? sq[7] : cq[7]) * ((x1 ^ x2) ? sq[6] : cq[6]);
        float f2_0 = x2 ? sq[5] : cq[5];     // v2 = x2 ^ b3
        float f2_1 = x2 ? cq[5] : sq[5];
        float f6_0 = x0 ? sq[1] : cq[1];     // v6 parity (b6^b7) selector
        float f6_1 = x0 ? cq[1] : sq[1];
        float f7_0 = x0 ? sq[0] : cq[0];     // v7 = x0 ^ b7
        float f7_1 = x0 ? cq[0] : sq[0];
        float A0 = Lbase * f2_0, A1 = Lbase * f2_1;
        // fold F3 (v3 = b3^b4): per slot, per b4
        float A00 = A0 * cq[4], A01 = A0 * sq[4];   // slot0: b4=0 / b4=1
        float A10 = A1 * sq[4], A11 = A1 * cq[4];   // slot1
        #pragma unroll
        for (int j = 0; j < 16; j++) {
            const int b4 = j & 1, b5 = (j >> 1) & 1, b6 = (j >> 2) & 1, b7 = (j >> 3) & 1;
            float w = ((b4 ^ b5) ? sq[3] : cq[3])
                    * ((b5 ^ b6) ? sq[2] : cq[2])
                    * ((b6 ^ b7) ? f6_1 : f6_0)
                    * (b7 ? f7_1 : f7_0);
            float l_ = (b4 ? A01 : A00) * w;
            float h_ = (b4 ? A11 : A10) * w;
            MK2(srp[j], l_, h_);
        }
    }

    // ---------------- Cycles 1..3: fused RY+CNOT ----------------
    #pragma unroll
    for (int k = 1; k < 4; k++) {
        float c_, s_;
        #define BCAST(q) { c_ = __shfl_sync(FULL, acv[k], gb | (q)); \
                           s_ = __shfl_sync(FULL, asv[k], gb | (q)); }

        // ---- bit7 gate (packs j <-> j+8); k>=2 fused with prev CNOT(0,7) ----
        BCAST(0)
        if (k == 1) {
            u64 CC = dup2(c_), SS = dup2(s_), NS = dup2(-s_);
            #pragma unroll
            for (int j = 0; j < 8; j++) {
                u64 a = srp[j], b = srp[j + 8];
                srp[j]     = paxpby(CC, a, NS, b);
                srp[j + 8] = paxpby(SS, a, CC, b);
            }
        } else {
            bool g = lane & 1;
            u64 AL0 = dup2(g ? -s_ : c_), GA0 = dup2(g ? c_ : -s_);
            u64 AL1 = dup2(g ?  s_ : c_), GA1 = dup2(g ? c_ :  s_);
            #pragma unroll
            for (int j = 0; j < 8; j++) {
                u64 a = srp[j], b = srp[j + 8];
                srp[j]     = paxpby(AL0, a, GA0, b);
                srp[j + 8] = paxpby(AL1, b, GA1, a);
            }
        }
        // ---- reg pack-pair gates: bit6 (dist4, swap j&8), bit5 (dist2, swap j&4),
        //      bit4 (dist1, swap j&2) ----
        #define RGATE(DIST, CB) {                                            \
            u64 CC = dup2(c_), SS = dup2(s_), NS = dup2(-s_);                \
            _Pragma("unroll")                                                \
            for (int j = 0; j < 16; j++) {                                   \
                if (!(j & (DIST))) {                                         \
                    const int j2 = j | (DIST);                               \
                    u64 a = srp[j], b = srp[j2];                             \
                    u64 n0 = paxpby(CC, a, NS, b);                           \
                    u64 n1 = paxpby(SS, a, CC, b);                           \
                    if (j & (CB)) { srp[j] = n1; srp[j2] = n0; }             \
                    else          { srp[j] = n0; srp[j2] = n1; }             \
                }                                                            \
            } }
        BCAST(1) RGATE(4, 8)
        BCAST(2) RGATE(2, 4)
        BCAST(3) RGATE(1, 2)
        #undef RGATE
        // ---- bit3 gate (within pack), CNOT swap if j&1 ----
        BCAST(4)
        {
            u64 CC = dup2(c_);
            u64 SV; MK2(SV, -s_, s_);   // no-swap: out = CC*a + SV*rev(a)
            u64 SW; MK2(SW, s_, -s_);   // swap:    out = CC*rev(a) + SW*a
            #pragma unroll
            for (int j = 0; j < 16; j++) {
                float a0, a1; UP2(a0, a1, srp[j]);
                u64 rv; MK2(rv, a1, a0);
                if (j & 1) srp[j] = paxpby(CC, rv, SW, srp[j]);
                else       srp[j] = paxpby(CC, srp[j], SV, rv);
            }
        }
        // ---- bit2 gate: lane mask 4, ctrl = slot (amp bit3) ----
        BCAST(5)
        {
            float t = ((lane >> 2) & 1) ? s_ : -s_;
            u64 ALv; MK2(ALv, c_, -t);
            u64 GAv; MK2(GAv, t, c_);
            #pragma unroll
            for (int j = 0; j < 16; j++) {
                u64 p = __shfl_xor_sync(FULL, srp[j], 4);
                srp[j] = paxpby(ALv, srp[j], GAv, p);
            }
        }
        // ---- lane gates: bit1 (ctrl lane2), bit0 (ctrl lane1) ----
        #define LGATE(B) {                                                   \
            float t = ((lane >> (B)) & 1) ? s_ : -s_;                        \
            bool  g = (lane >> ((B) + 1)) & 1;                               \
            u64 AL = dup2(g ? -t : c_);                                      \
            u64 GA = dup2(g ?  c_ : t);                                      \
            _Pragma("unroll")                                                \
            for (int j = 0; j < 16; j++) {                                   \
                u64 p = __shfl_xor_sync(FULL, srp[j], 1 << (B));             \
                srp[j] = paxpby(AL, srp[j], GA, p);                          \
            } }
        BCAST(6) LGATE(1)
        BCAST(7) LGATE(0)
        #undef LGATE
        #undef BCAST
    }
    // Cycle 3's trailing CNOT(0,7): conditional pack swap (j <-> j+8)
    {
        bool g = lane & 1;
        #pragma unroll
        for (int j = 0; j < 8; j++) {
            u64 a = srp[j], b = srp[j + 8];
            srp[j]     = g ? b : a;
            srp[j + 8] = g ? a : b;
        }
    }

    // ---------------- 10 CRX gates ----------------
    // (ctrl bit, tgt bit) = (7-i%8, 7-(i+1)%8).  si starts logically 0; every
    // sip[] is written before first read (verified pack-by-pack), no init.
    #define CBC(i) float co, sn;                                             \
        if ((i) < 8) { co = __shfl_sync(FULL, ccoA, gb | (i));               \
                       sn = __shfl_sync(FULL, csnA, gb | (i)); }             \
        else         { co = __shfl_sync(FULL, ccoB, gb | ((i) - 8));         \
                       sn = __shfl_sync(FULL, csnB, gb | ((i) - 8)); }

    // CRX0: ctrl bit7 (j&8), tgt bit6 -> pairs (8,12),(9,13),(10,14),(11,15); RE
    { CBC(0)
      u64 CO = dup2(co), NSN = dup2(-sn);
      #pragma unroll
      for (int j = 8; j < 12; j++) {
          const int jb = j + 4;
          u64 a = srp[j], b = srp[jb];
          PMUL(srp[j],  CO,  a);  PMUL(sip[j],  NSN, b);
          PMUL(srp[jb], CO,  b);  PMUL(sip[jb], NSN, a);
      } }
    // CRX1: ctrl bit6 (j&4), tgt bit5 -> (4,6),(5,7) RE + (12,14),(13,15) FULL
    { CBC(1)
      u64 CO = dup2(co), SN = dup2(sn), NSN = dup2(-sn);
      #pragma unroll
      for (int j = 4; j < 6; j++) {
          const int jb = j + 2;
          u64 a = srp[j], b = srp[jb];
          PMUL(srp[j],  CO, a);  PMUL(sip[j],  NSN, b);
          PMUL(srp[jb], CO, b);  PMUL(sip[jb], NSN, a);
      }
      #pragma unroll
      for (int j = 12; j < 14; j++) {
          const int jb = j + 2;
          u64 ar = srp[j], ai = sip[j], br = srp[jb], bi = sip[jb];
          srp[j]  = paxpby(CO, ar, SN,  bi);  sip[j]  = paxpby(CO, ai, NSN, br);
          srp[jb] = paxpby(CO, br, SN,  ai);  sip[jb] = paxpby(CO, bi, NSN, ar);
      } }
    // CRX2: ctrl bit5 (j&2), tgt bit4 -> (2,3) RE + (6,7),(10,11),(14,15) FULL
    { CBC(2)
      u64 CO = dup2(co), SN = dup2(sn), NSN = dup2(-sn);
      { u64 a = srp[2], b = srp[3];
        PMUL(srp[2], CO, a);  PMUL(sip[2], NSN, b);
        PMUL(srp[3], CO, b);  PMUL(sip[3], NSN, a); }
      #pragma unroll
      for (int j = 6; j < 16; j += 4) {
          const int jb = j + 1;
          u64 ar = srp[j], ai = sip[j], br = srp[jb], bi = sip[jb];
          srp[j]  = paxpby(CO, ar, SN,  bi);  sip[j]  = paxpby(CO, ai, NSN, br);
          srp[jb] = paxpby(CO, br, SN,  ai);  sip[jb] = paxpby(CO, bi, NSN, ar);
      } }
    // CRX3: ctrl bit4 (j&1, odd packs), tgt bit3 (within pack); pack1 RE, rest FULL
    { CBC(3)
      u64 CO = dup2(co), SN = dup2(sn), NSN = dup2(-sn);
      { float a0, a1; UP2(a0, a1, srp[1]);
        u64 rv; MK2(rv, a1, a0);
        PMUL(srp[1], CO, srp[1]);
        PMUL(sip[1], NSN, rv); }
      #pragma unroll
      for (int j = 3; j < 16; j += 2) {
          float r0, r1, i0, i1;
          UP2(r0, r1, srp[j]);  UP2(i0, i1, sip[j]);
          u64 rvr; MK2(rvr, r1, r0);
          u64 rvi; MK2(rvi, i1, i0);
          srp[j] = paxpby(CO, srp[j], SN,  rvi);
          sip[j] = paxpby(CO, sip[j], NSN, rvr);
      } }
    // CRX4: ctrl bit3 (slot), tgt bit2 (lane mask 4); per-slot coeffs (1,co)/(0,sn)
    { CBC(4)
      u64 COe; MK2(COe, 1.0f, co);
      u64 SNe; MK2(SNe, 0.0f, sn);
      u64 NSNe; MK2(NSNe, 0.0f, -sn);
      { // pack 0: si still zero -> skip si shuffle
        u64 pr = __shfl_xor_sync(FULL, srp[0], 4);
        u64 t = srp[0];
        PMUL(srp[0], COe, t);
        PMUL(sip[0], NSNe, pr); }
      #pragma unroll
      for (int j = 1; j < 16; j++) {
          u64 pr = __shfl_xor_sync(FULL, srp[j], 4);
          u64 pi = __shfl_xor_sync(FULL, sip[j], 4);
          srp[j] = paxpby(COe, srp[j], SNe,  pi);
          sip[j] = paxpby(COe, sip[j], NSNe, pr);
      } }
    // CRX5/6: lane ctrl, lane target (fold ctrl into coefficients)
    #define CRXL(CB, MASK) {                                                 \
        bool  g    = (lane >> (CB)) & 1;                                     \
        float co_e = g ? co : 1.0f;                                          \
        float sn_e = g ? sn : 0.0f;                                          \
        u64 COe = dup2(co_e), SNe = dup2(sn_e), NSNe = dup2(-sn_e);          \
        _Pragma("unroll")                                                    \
        for (int j = 0; j < 16; j++) {                                       \
            u64 pr = __shfl_xor_sync(FULL, srp[j], MASK);                    \
            u64 pi = __shfl_xor_sync(FULL, sip[j], MASK);                    \
            srp[j] = paxpby(COe, srp[j], SNe,  pi);                          \
            sip[j] = paxpby(COe, sip[j], NSNe, pr);                          \
        } }
    { CBC(5) CRXL(2, 2) }
    { CBC(6) CRXL(1, 1) }
    #undef CRXL
    // CRX7: ctrl lane bit0, tgt bit7 -> pairs (j, j+8), folded coefficients
    { CBC(7)
      bool  g    = lane & 1;
      float co_e = g ? co : 1.0f;
      float sn_e = g ? sn : 0.0f;
      u64 COe = dup2(co_e), SNe = dup2(sn_e), NSNe = dup2(-sn_e);
      #pragma unroll
      for (int j = 0; j < 8; j++) {
          u64 ar = srp[j], ai = sip[j], br = srp[j + 8], bi = sip[j + 8];
          srp[j]     = paxpby(COe, ar, SNe,  bi);
          sip[j]     = paxpby(COe, ai, NSNe, br);
          srp[j + 8] = paxpby(COe, br, SNe,  ai);
          sip[j + 8] = paxpby(COe, bi, NSNe, ar);
      } }
    // CRX8: ctrl bit7 (j&8), tgt bit6 -> (8,12),(9,13),(10,14),(11,15) FULL
    { CBC(8)
      u64 CO = dup2(co), SN = dup2(sn), NSN = dup2(-sn);
      #pragma unroll
      for (int j = 8; j < 12; j++) {
          const int jb = j + 4;
          u64 ar = srp[j], ai = sip[j], br = srp[jb], bi = sip[jb];
          srp[j]  = paxpby(CO, ar, SN,  bi);  sip[j]  = paxpby(CO, ai, NSN, br);
          srp[jb] = paxpby(CO, br, SN,  ai);  sip[jb] = paxpby(CO, bi, NSN, ar);
      } }
    // CRX9: ctrl bit6 (j&4), tgt bit5 -> (4,6),(5,7),(12,14),(13,15) FULL
    { CBC(9)
      u64 CO = dup2(co), SN = dup2(sn), NSN = dup2(-sn);
      #pragma unroll
      for (int jj = 0; jj < 4; jj++) {
          const int j  = (jj & 1) + (jj & 2 ? 12 : 4);
          const int jb = j + 2;
          u64 ar = srp[j], ai = sip[j], br = srp[jb], bi = sip[jb];
          srp[j]  = paxpby(CO, ar, SN,  bi);  sip[j]  = paxpby(CO, ai, NSN, br);
          srp[jb] = paxpby(CO, br, SN,  ai);  sip[jb] = paxpby(CO, bi, NSN, ar);
      } }
    #undef CBC

    // ---------------- Measurement + MLP ----------------
    // qubit3 = amp bit4 = pack bit0 (even packs +); qubit7 = amp bit0 = lane bit0.
    u64 accE, accO;
    { float z0 = 0.0f; MK2(accE, z0, z0); MK2(accO, z0, z0); }
    #pragma unroll
    for (int j = 0; j < 16; j += 2) {
        PFMA(accE, srp[j], srp[j], accE);
        PFMA(accE, sip[j], sip[j], accE);
        PFMA(accO, srp[j + 1], srp[j + 1], accO);
        PFMA(accO, sip[j + 1], sip[j + 1], accO);
    }
    float e_lo, e_hi, o_lo, o_hi;
    UP2(e_lo, e_hi, accE);  UP2(o_lo, o_hi, accO);
    float SE = e_lo + e_hi, SO = o_lo + o_hi;

    float f0  = SE - SO;
    float tot = SE + SO;
    float f1  = (lane & 1) ? -tot : tot;
    u64 fv; MK2(fv, f0, f1);
    #pragma unroll
    for (int m = 4; m >= 1; m >>= 1) {
        u64 p = __shfl_xor_sync(FULL, fv, m);
        PADD(fv, fv, p);
    }
    UP2(f0, f1, fv);

    // Hidden units: lane lo handles unit lo; lanes 0,1 also units 8,9.
    float z1 = fmaf(f0, __ldg(&w1[lo * 2 + 0]),
               fmaf(f1, __ldg(&w1[lo * 2 + 1]), __ldg(&b1[lo])));
    float contrib = tanhf(z1) * __ldg(&w2[lo]);
    if (lo < 2) {
        const int u = 8 + lo;
        float z2 = fmaf(f0, __ldg(&w1[u * 2 + 0]),
                   fmaf(f1, __ldg(&w1[u * 2 + 1]), __ldg(&b1[u])));
        contrib += tanhf(z2) * __ldg(&w2[u]);
    }
    #pragma unroll
    for (int m = 4; m >= 1; m >>= 1)
        contrib += __shfl_xor_sync(FULL, contrib, m);

    if (lo == 0 && em < n_batch) {
        float z = contrib + __ldg(&b2[0]);
        out[em] = 1.0f / (1.0f + __expf(-z));
    }
}

extern "C" void kernel_launch(void* const* d_in, const int* in_sizes, int n_in,
                              void* d_out, int out_size) {
    const float* x         = (const float*)d_in[0];
    const float* crx_theta = (const float*)d_in[1];
    const float* w1        = (const float*)d_in[2];
    const float* b1        = (const float*)d_in[3];
    const float* w2        = (const float*)d_in[4];
    const float* b2        = (const float*)d_in[5];
    float* out = (float*)d_out;

    const int n_batch = in_sizes[0] / 32;            // (B,4,8) -> B
    const int nwarps  = (n_batch + 3) / 4;           // 4 elements per warp
    const int threads = 128;                         // 4 warps per block
    const int blocks  = (nwarps + 3) / 4;
    vqc_kernel<<<blocks, threads>>>(x, crx_theta, w1, b1, w2, b2, out, n_batch);
}